// round 1
// baseline (speedup 1.0000x reference)
#include <cuda_runtime.h>
#include <math.h>

// Problem constants (fixed by setup_inputs)
#define MROWS (64 * 2048)   // B*N = 131072
#define KDIM 512            // D
#define NDIM 512            // H
#define NNODES 2048         // N
#define BN_EPS 1e-5

// Scratch (device globals: allocation-free)
__device__ float  g_h[(size_t)MROWS * NDIM];   // 256 MB hidden activations
__device__ double g_sum[NDIM];
__device__ double g_sumsq[NDIM];
__device__ float  g_a[NDIM];                   // gamma * inv_std
__device__ float  g_c[NDIM];                   // beta - mu * a

// ---------------------------------------------------------------------------
// Kernel 0: zero the stats accumulators (must reset on every graph replay)
// ---------------------------------------------------------------------------
__global__ void init_kernel() {
    int t = blockIdx.x * blockDim.x + threadIdx.x;
    if (t < NDIM) { g_sum[t] = 0.0; g_sumsq[t] = 0.0; }
}

// ---------------------------------------------------------------------------
// Kernel 1: h = x @ W1 + b1   (fp32, 128x128x8 tiles, double-buffered smem)
// Fused: store h to scratch + per-column sum/sumsq partials (fp64 atomics).
// ---------------------------------------------------------------------------
__global__ __launch_bounds__(256, 2)
void gemm_stats_kernel(const float* __restrict__ A,   // x   [MROWS, KDIM]
                       const float* __restrict__ Bw,  // W1  [KDIM, NDIM]
                       const float* __restrict__ bias) // b1 [NDIM]
{
    constexpr int BM = 128, BN = 128, BK = 8;
    __shared__ float sA[2][BK][BM];   // A tile transposed: [k][m]
    __shared__ float sB[2][BK][BN];

    const int tid = threadIdx.x;
    const int bm = blockIdx.y * BM;
    const int bn = blockIdx.x * BN;

    // global->shared load mapping (one float4 per tile per thread)
    const int arow = tid >> 1;             // 0..127
    const int acol = (tid & 1) * 4;        // 0 or 4
    const int brow = tid >> 5;             // 0..7
    const int bcol = (tid & 31) * 4;       // 0..124

    const float* Ap = A + (size_t)(bm + arow) * KDIM + acol;
    const float* Bp = Bw + (size_t)brow * NDIM + bn + bcol;

    // prologue: fill buffer 0
    float4 av = *(const float4*)Ap;
    float4 bv = *(const float4*)Bp;
    sA[0][acol + 0][arow] = av.x;
    sA[0][acol + 1][arow] = av.y;
    sA[0][acol + 2][arow] = av.z;
    sA[0][acol + 3][arow] = av.w;
    *(float4*)&sB[0][brow][bcol] = bv;
    __syncthreads();

    const int ty = tid >> 4;   // 0..15 (row group)
    const int tx = tid & 15;   // 0..15 (col group)

    float acc[8][8];
    #pragma unroll
    for (int i = 0; i < 8; ++i)
        #pragma unroll
        for (int j = 0; j < 8; ++j) acc[i][j] = 0.f;

    const int NK = KDIM / BK;  // 64
    #pragma unroll 1
    for (int kt = 0; kt < NK; ++kt) {
        const int cur = kt & 1;
        if (kt + 1 < NK) {   // prefetch next k-block from global
            av = *(const float4*)(Ap + (kt + 1) * BK);
            bv = *(const float4*)(Bp + (size_t)(kt + 1) * BK * NDIM);
        }
        #pragma unroll
        for (int k = 0; k < BK; ++k) {
            float ar[8], br[8];
            *(float4*)&ar[0] = *(const float4*)&sA[cur][k][ty * 8];
            *(float4*)&ar[4] = *(const float4*)&sA[cur][k][ty * 8 + 4];
            *(float4*)&br[0] = *(const float4*)&sB[cur][k][tx * 8];
            *(float4*)&br[4] = *(const float4*)&sB[cur][k][tx * 8 + 4];
            #pragma unroll
            for (int i = 0; i < 8; ++i)
                #pragma unroll
                for (int j = 0; j < 8; ++j)
                    acc[i][j] = fmaf(ar[i], br[j], acc[i][j]);
        }
        if (kt + 1 < NK) {   // stage into the other buffer
            const int nxt = cur ^ 1;
            sA[nxt][acol + 0][arow] = av.x;
            sA[nxt][acol + 1][arow] = av.y;
            sA[nxt][acol + 2][arow] = av.z;
            sA[nxt][acol + 3][arow] = av.w;
            *(float4*)&sB[nxt][brow][bcol] = bv;
        }
        __syncthreads();
    }

    // epilogue: add bias, write h, accumulate column stats
    float bvals[8];
    #pragma unroll
    for (int j = 0; j < 8; ++j) bvals[j] = bias[bn + tx * 8 + j];

    float psum[8], psq[8];
    #pragma unroll
    for (int j = 0; j < 8; ++j) { psum[j] = 0.f; psq[j] = 0.f; }

    #pragma unroll
    for (int i = 0; i < 8; ++i) {
        const size_t row = (size_t)(bm + ty * 8 + i);
        float v[8];
        #pragma unroll
        for (int j = 0; j < 8; ++j) {
            v[j] = acc[i][j] + bvals[j];
            psum[j] += v[j];
            psq[j] = fmaf(v[j], v[j], psq[j]);
        }
        float* op = g_h + row * NDIM + bn + tx * 8;
        *(float4*)op       = make_float4(v[0], v[1], v[2], v[3]);
        *(float4*)(op + 4) = make_float4(v[4], v[5], v[6], v[7]);
    }

    // block-level column reduction (reuse sA: exactly 2048 floats)
    __syncthreads();
    float* red = &sA[0][0][0];
    #pragma unroll
    for (int j = 0; j < 8; ++j) red[(tx * 8 + j) * 16 + ty] = psum[j];
    __syncthreads();
    if (tid < 128) {
        double s = 0.0;
        #pragma unroll
        for (int t = 0; t < 16; ++t) s += (double)red[tid * 16 + t];
        atomicAdd(&g_sum[bn + tid], s);
    }
    __syncthreads();
    #pragma unroll
    for (int j = 0; j < 8; ++j) red[(tx * 8 + j) * 16 + ty] = psq[j];
    __syncthreads();
    if (tid < 128) {
        double s = 0.0;
        #pragma unroll
        for (int t = 0; t < 16; ++t) s += (double)red[tid * 16 + t];
        atomicAdd(&g_sumsq[bn + tid], s);
    }
}

// ---------------------------------------------------------------------------
// Kernel 2: finalize BN affine params: a = gamma*rsqrt(var+eps), c = beta-mu*a
// ---------------------------------------------------------------------------
__global__ void finalize_kernel(const float* __restrict__ gamma,
                                const float* __restrict__ beta) {
    const int t = threadIdx.x;  // 512 threads, 1 block
    const double mu  = g_sum[t]   / (double)MROWS;
    const double var = g_sumsq[t] / (double)MROWS - mu * mu;
    const float a = gamma[t] * (float)(1.0 / sqrt(var + BN_EPS));
    g_a[t] = a;
    g_c[t] = beta[t] - (float)mu * a;
}

// ---------------------------------------------------------------------------
// Kernel 3: per-row BN+ReLU, head logits, argmax. Warp per row, 4 rows/warp.
// head = (n >= N/2): idx_a/idx_b are fixed contiguous halves for this seed.
// ---------------------------------------------------------------------------
__global__ __launch_bounds__(256)
void heads_kernel(const float* __restrict__ Wa, const float* __restrict__ ba,
                  const float* __restrict__ Wb, const float* __restrict__ bb,
                  float* __restrict__ out) {
    __shared__ float4 sW[8][128];   // rows 0-2: Wa columns; rows 3-7: Wb columns
    __shared__ float  sbias[8];

    const int tid = threadIdx.x;
    for (int i = tid; i < 8 * 128; i += 256) {
        const int c = i >> 7;      // 0..7
        const int f4 = i & 127;
        const int h = f4 * 4;
        float4 w;
        if (c < 3) {
            w.x = Wa[(h + 0) * 3 + c];
            w.y = Wa[(h + 1) * 3 + c];
            w.z = Wa[(h + 2) * 3 + c];
            w.w = Wa[(h + 3) * 3 + c];
        } else {
            const int cb = c - 3;
            w.x = Wb[(h + 0) * 5 + cb];
            w.y = Wb[(h + 1) * 5 + cb];
            w.z = Wb[(h + 2) * 5 + cb];
            w.w = Wb[(h + 3) * 5 + cb];
        }
        sW[c][f4] = w;
    }
    if (tid < 3)      sbias[tid] = ba[tid];
    else if (tid < 8) sbias[tid] = bb[tid - 3];
    __syncthreads();

    const int warp = tid >> 5, lane = tid & 31;

    // per-lane BN params for its fixed column slots
    float4 areg[4], creg[4];
    #pragma unroll
    for (int w = 0; w < 4; ++w) {
        const int col = (w * 32 + lane) * 4;
        areg[w] = *(const float4*)&g_a[col];
        creg[w] = *(const float4*)&g_c[col];
    }

    const int base = blockIdx.x * 32 + warp * 4;
    #pragma unroll 1
    for (int r = 0; r < 4; ++r) {
        const int row = base + r;
        const int node = row & (NNODES - 1);
        const int head = (node >= NNODES / 2) ? 1 : 0;
        const float4* hp = (const float4*)(g_h + (size_t)row * NDIM);

        float a0 = 0.f, a1 = 0.f, a2 = 0.f, a3 = 0.f, a4 = 0.f;
        #pragma unroll
        for (int w = 0; w < 4; ++w) {
            const int f4 = w * 32 + lane;
            const float4 hv = hp[f4];
            const float r0 = fmaxf(fmaf(hv.x, areg[w].x, creg[w].x), 0.f);
            const float r1 = fmaxf(fmaf(hv.y, areg[w].y, creg[w].y), 0.f);
            const float r2 = fmaxf(fmaf(hv.z, areg[w].z, creg[w].z), 0.f);
            const float r3 = fmaxf(fmaf(hv.w, areg[w].w, creg[w].w), 0.f);
            if (head == 0) {
                float4 w0 = sW[0][f4], w1 = sW[1][f4], w2 = sW[2][f4];
                a0 = fmaf(r0, w0.x, fmaf(r1, w0.y, fmaf(r2, w0.z, fmaf(r3, w0.w, a0))));
                a1 = fmaf(r0, w1.x, fmaf(r1, w1.y, fmaf(r2, w1.z, fmaf(r3, w1.w, a1))));
                a2 = fmaf(r0, w2.x, fmaf(r1, w2.y, fmaf(r2, w2.z, fmaf(r3, w2.w, a2))));
            } else {
                float4 w0 = sW[3][f4], w1 = sW[4][f4], w2 = sW[5][f4],
                       w3 = sW[6][f4], w4 = sW[7][f4];
                a0 = fmaf(r0, w0.x, fmaf(r1, w0.y, fmaf(r2, w0.z, fmaf(r3, w0.w, a0))));
                a1 = fmaf(r0, w1.x, fmaf(r1, w1.y, fmaf(r2, w1.z, fmaf(r3, w1.w, a1))));
                a2 = fmaf(r0, w2.x, fmaf(r1, w2.y, fmaf(r2, w2.z, fmaf(r3, w2.w, a2))));
                a3 = fmaf(r0, w3.x, fmaf(r1, w3.y, fmaf(r2, w3.z, fmaf(r3, w3.w, a3))));
                a4 = fmaf(r0, w4.x, fmaf(r1, w4.y, fmaf(r2, w4.z, fmaf(r3, w4.w, a4))));
            }
        }
        #pragma unroll
        for (int off = 16; off; off >>= 1) {
            a0 += __shfl_xor_sync(0xffffffffu, a0, off);
            a1 += __shfl_xor_sync(0xffffffffu, a1, off);
            a2 += __shfl_xor_sync(0xffffffffu, a2, off);
            a3 += __shfl_xor_sync(0xffffffffu, a3, off);
            a4 += __shfl_xor_sync(0xffffffffu, a4, off);
        }
        if (lane == 0) {
            const int cbase = head ? 3 : 0;
            const int nc = head ? 5 : 3;
            float l[5] = {a0, a1, a2, a3, a4};
            float best = l[0] + sbias[cbase];
            int bi = 0;
            #pragma unroll
            for (int c = 1; c < 5; ++c) {
                if (c < nc) {
                    const float v = l[c] + sbias[cbase + c];
                    if (v > best) { best = v; bi = c; }  // strict > : first-max wins (matches argmax)
                }
            }
            out[row] = (float)bi;
        }
    }
}

// ---------------------------------------------------------------------------
// Launch sequence (graph-capturable: kernel launches only)
// Inputs: x, W1, b1, gamma, beta, Wa, ba, Wb, bb, idx_a, idx_b
// ---------------------------------------------------------------------------
extern "C" void kernel_launch(void* const* d_in, const int* in_sizes, int n_in,
                              void* d_out, int out_size) {
    const float* x     = (const float*)d_in[0];
    const float* W1    = (const float*)d_in[1];
    const float* b1    = (const float*)d_in[2];
    const float* gamma = (const float*)d_in[3];
    const float* beta  = (const float*)d_in[4];
    const float* Wa    = (const float*)d_in[5];
    const float* ba    = (const float*)d_in[6];
    const float* Wb    = (const float*)d_in[7];
    const float* bb    = (const float*)d_in[8];
    float* out = (float*)d_out;

    init_kernel<<<2, 256>>>();
    dim3 grid(NDIM / 128, MROWS / 128);   // (4, 1024)
    gemm_stats_kernel<<<grid, 256>>>(x, W1, b1);
    finalize_kernel<<<1, 512>>>(gamma, beta);
    heads_kernel<<<MROWS / 32, 256>>>(Wa, ba, Wb, bb, out);
}

// round 5
// speedup vs baseline: 1.4914x; 1.4914x over previous
#include <cuda_runtime.h>
#include <cuda_fp16.h>
#include <math.h>
#include <stdint.h>

// Problem constants (fixed by setup_inputs)
#define MROWS (64 * 2048)   // B*N = 131072
#define KDIM 512            // D
#define NDIM 512            // H
#define NNODES 2048
#define BN_EPS 1e-5

// GEMM tiling
#define BM 128
#define BN 256
#define BK 64
#define NCHUNK (KDIM / BK)     // 8
#define GTHREADS 512           // 16 warps: 2 (M) x 8 (N), warp tile 64x32

// smem stage layout (bytes): A planes 2x16K, B planes 2x32K -> 96K/stage
#define STAGE_BYTES 98304
#define A_PLANE     16384
#define B_OFF       32768
#define B_PLANE     32768
#define SMEM_DYN    (2 * STAGE_BYTES)   // 192 KB
#define SCW         260                 // epilogue fp32 stride (128x260 = 133KB)

// Scratch (device globals: allocation-free)
__device__ float  g_h[(size_t)MROWS * NDIM];           // 256 MB
__device__ __half g_xa[2][(size_t)MROWS * KDIM];       // x splits, [m][k]
__device__ __half g_wb[2][(size_t)NDIM * KDIM];        // W1^T splits, [n][k]
__device__ double g_sum[NDIM];
__device__ double g_sumsq[NDIM];
__device__ float  g_a[NDIM];
__device__ float  g_c[NDIM];

// ---------------------------------------------------------------------------
// PTX helpers (all base-target instructions: sm_80 era)
// ---------------------------------------------------------------------------
__device__ __forceinline__ uint32_t smem_u32(const void* p) {
    return (uint32_t)__cvta_generic_to_shared(p);
}

#define CP_ASYNC16(dst, src) \
    asm volatile("cp.async.cg.shared.global [%0], [%1], 16;" :: "r"(dst), "l"(src))
#define CP_COMMIT() asm volatile("cp.async.commit_group;" ::: "memory")
#define CP_WAIT(n)  asm volatile("cp.async.wait_group %0;" :: "n"(n) : "memory")

__device__ __forceinline__ void ldsm4(uint32_t& r0, uint32_t& r1,
                                      uint32_t& r2, uint32_t& r3, uint32_t addr) {
    asm volatile("ldmatrix.sync.aligned.m8n8.x4.shared.b16 {%0,%1,%2,%3}, [%4];"
                 : "=r"(r0), "=r"(r1), "=r"(r2), "=r"(r3) : "r"(addr));
}

__device__ __forceinline__ void mma16816(float* c, const uint32_t* a, const uint32_t* b) {
    asm volatile(
        "mma.sync.aligned.m16n8k16.row.col.f32.f16.f16.f32 "
        "{%0,%1,%2,%3}, {%4,%5,%6,%7}, {%8,%9}, {%0,%1,%2,%3};"
        : "+f"(c[0]), "+f"(c[1]), "+f"(c[2]), "+f"(c[3])
        : "r"(a[0]), "r"(a[1]), "r"(a[2]), "r"(a[3]), "r"(b[0]), "r"(b[1]));
}

// ---------------------------------------------------------------------------
// fp32 -> 2x fp16 split kernels
// ---------------------------------------------------------------------------
union HF4 { __half h[4]; uint2 u; };

__global__ __launch_bounds__(256) void split_x_kernel(const float* __restrict__ x) {
    size_t i = ((size_t)blockIdx.x * 256 + threadIdx.x) * 4;
    float4 v = *(const float4*)(x + i);
    float f[4] = {v.x, v.y, v.z, v.w};
    HF4 p0, p1;
    #pragma unroll
    for (int j = 0; j < 4; ++j) {
        __half h0 = __float2half_rn(f[j]);
        float r = f[j] - __half2float(h0);
        p0.h[j] = h0;
        p1.h[j] = __float2half_rn(r);
    }
    *(uint2*)&g_xa[0][i] = p0.u;
    *(uint2*)&g_xa[1][i] = p1.u;
}

// W1 [K, N] -> transposed split planes [n][k]
__global__ __launch_bounds__(256) void split_w_kernel(const float* __restrict__ W1) {
    int idx = blockIdx.x * 256 + threadIdx.x;   // idx = n*512 + k
    int n = idx >> 9, k = idx & 511;
    float t = W1[(size_t)k * NDIM + n];
    __half h0 = __float2half_rn(t);
    float r = t - __half2float(h0);
    g_wb[0][idx] = h0;
    g_wb[1][idx] = __float2half_rn(r);
}

// ---------------------------------------------------------------------------
// Kernel 0: zero stats accumulators (reset on every graph replay)
// ---------------------------------------------------------------------------
__global__ void init_kernel() {
    int t = blockIdx.x * blockDim.x + threadIdx.x;
    if (t < NDIM) { g_sum[t] = 0.0; g_sumsq[t] = 0.0; }
}

// ---------------------------------------------------------------------------
// GEMM: h = x @ W1 + b1 via 3-product fp16x2 emulation on mma.sync (HMMA).
// 128x256 CTA tile, BK=64, 2-stage cp.async pipeline, SW128 swizzle.
// Fused epilogue: bias, store h, column sum/sumsq (fp64 atomics).
// ---------------------------------------------------------------------------
__device__ __forceinline__ void issue_loads(uint32_t sbase, int st, int kt,
                                            int bm, int bn, int tid) {
    const uint32_t stoff = sbase + st * STAGE_BYTES;
    const size_t kbyte = (size_t)kt * BK * 2;   // 128 bytes per chunk-row
    #pragma unroll
    for (int s = 0; s < 2; ++s) {
        // A plane: 128 rows x 128B = 1024 chunks of 16B
        const char* asrc = (const char*)g_xa[s] + (size_t)bm * KDIM * 2 + kbyte;
        uint32_t adst = stoff + s * A_PLANE;
        #pragma unroll
        for (int i = 0; i < 2; ++i) {
            int c = tid + i * GTHREADS;
            int row = c >> 3, seg = (c & 7) * 16;
            CP_ASYNC16(adst + row * 128 + (seg ^ ((row & 7) << 4)),
                       asrc + (size_t)row * KDIM * 2 + seg);
        }
        // B plane: 256 rows x 128B = 2048 chunks
        const char* bsrc = (const char*)g_wb[s] + (size_t)bn * KDIM * 2 + kbyte;
        uint32_t bdst = stoff + B_OFF + s * B_PLANE;
        #pragma unroll
        for (int i = 0; i < 4; ++i) {
            int c = tid + i * GTHREADS;
            int row = c >> 3, seg = (c & 7) * 16;
            CP_ASYNC16(bdst + row * 128 + (seg ^ ((row & 7) << 4)),
                       bsrc + (size_t)row * KDIM * 2 + seg);
        }
    }
    CP_COMMIT();
}

__global__ __launch_bounds__(GTHREADS, 1)
void gemm_tc_kernel(const float* __restrict__ bias) {
    extern __shared__ char dynsmem[];
    __shared__ float sbias[BN];

    const int tid = threadIdx.x;
    const int bn = blockIdx.x * BN;
    const int bm = blockIdx.y * BM;
    const uint32_t sbase = smem_u32(dynsmem);

    if (tid < BN) sbias[tid] = bias[bn + tid];

    const int wid = tid >> 5, l = tid & 31;
    const int wm = wid >> 3;          // 0..1 -> m offset 64
    const int wn = wid & 7;           // 0..7 -> n offset 32
    const uint32_t xorL = (l & 7) << 4;
    const uint32_t aRowOff = (uint32_t)(wm * 8192 + (l & 15) * 128);
    const uint32_t bRowOff = (uint32_t)(wn * 4096 + ((l & 7) + ((l >> 4) << 3)) * 128);

    float c[4][4][4];
    #pragma unroll
    for (int mi = 0; mi < 4; ++mi)
        #pragma unroll
        for (int nj = 0; nj < 4; ++nj)
            #pragma unroll
            for (int r = 0; r < 4; ++r) c[mi][nj][r] = 0.f;

    // prologue: fill both stages
    issue_loads(sbase, 0, 0, bm, bn, tid);
    issue_loads(sbase, 1, 1, bm, bn, tid);

    const int pa[3] = {0, 0, 1};
    const int pb[3] = {0, 1, 0};

    #pragma unroll 1
    for (int kt = 0; kt < NCHUNK; ++kt) {
        const int st = kt & 1;
        if (kt < NCHUNK - 1) { CP_WAIT(1); } else { CP_WAIT(0); }
        __syncthreads();

        const uint32_t stoff = sbase + st * STAGE_BYTES;
        #pragma unroll
        for (int p = 0; p < 3; ++p) {
            const uint32_t aBase = stoff + pa[p] * A_PLANE + aRowOff;
            const uint32_t bBase = stoff + B_OFF + pb[p] * B_PLANE + bRowOff;
            #pragma unroll
            for (int ks = 0; ks < 4; ++ks) {
                const uint32_t aCol = (uint32_t)((ks << 5) + ((l >> 4) << 4)) ^ xorL;
                const uint32_t bCol = (uint32_t)((ks << 5) + (((l >> 3) & 1) << 4)) ^ xorL;
                uint32_t a[4][4], b[2][4];
                #pragma unroll
                for (int mi = 0; mi < 4; ++mi)
                    ldsm4(a[mi][0], a[mi][1], a[mi][2], a[mi][3],
                          aBase + mi * 2048 + aCol);
                #pragma unroll
                for (int jj = 0; jj < 2; ++jj)
                    ldsm4(b[jj][0], b[jj][1], b[jj][2], b[jj][3],
                          bBase + jj * 2048 + bCol);
                #pragma unroll
                for (int mi = 0; mi < 4; ++mi) {
                    mma16816(c[mi][0], a[mi], &b[0][0]);
                    mma16816(c[mi][1], a[mi], &b[0][2]);
                    mma16816(c[mi][2], a[mi], &b[1][0]);
                    mma16816(c[mi][3], a[mi], &b[1][2]);
                }
            }
        }
        __syncthreads();
        if (kt + 2 < NCHUNK) issue_loads(sbase, st, kt + 2, bm, bn, tid);
    }

    // ---------------- epilogue: accum -> smem (bias added) ----------------
    float* sC = (float*)dynsmem;
    const int qrow = l >> 2, qcol = (l & 3) * 2;
    #pragma unroll
    for (int mi = 0; mi < 4; ++mi) {
        #pragma unroll
        for (int nj = 0; nj < 4; ++nj) {
            const int m = wm * 64 + mi * 16 + qrow;
            const int n = wn * 32 + nj * 8 + qcol;
            const float b0 = sbias[n], b1 = sbias[n + 1];
            float2 v01 = make_float2(c[mi][nj][0] + b0, c[mi][nj][1] + b1);
            float2 v23 = make_float2(c[mi][nj][2] + b0, c[mi][nj][3] + b1);
            *(float2*)&sC[m * SCW + n] = v01;
            *(float2*)&sC[(m + 8) * SCW + n] = v23;
        }
    }
    __syncthreads();

    // store h (coalesced) : thread -> (row, 64-col segment)
    {
        const int row = tid >> 2;
        const int seg = (tid & 3) * 64;
        const float* src = &sC[row * SCW + seg];
        float* dst = g_h + (size_t)(bm + row) * NDIM + bn + seg;
        #pragma unroll
        for (int q = 0; q < 16; ++q)
            *(float4*)(dst + q * 4) = *(const float4*)(src + q * 4);
    }

    // column stats: 256 threads, one column each (conflict-free: stride 260)
    if (tid < BN) {
        float s = 0.f, q = 0.f;
        #pragma unroll 8
        for (int r = 0; r < BM; ++r) {
            float t = sC[r * SCW + tid];
            s += t;
            q = fmaf(t, t, q);
        }
        atomicAdd(&g_sum[bn + tid], (double)s);
        atomicAdd(&g_sumsq[bn + tid], (double)q);
    }
}

// ---------------------------------------------------------------------------
// Kernel 2: finalize BN affine params
// ---------------------------------------------------------------------------
__global__ void finalize_kernel(const float* __restrict__ gamma,
                                const float* __restrict__ beta) {
    const int t = threadIdx.x;  // 512 threads, 1 block
    const double mu  = g_sum[t]   / (double)MROWS;
    const double var = g_sumsq[t] / (double)MROWS - mu * mu;
    const float a = gamma[t] * (float)(1.0 / sqrt(var + BN_EPS));
    g_a[t] = a;
    g_c[t] = beta[t] - (float)mu * a;
}

// ---------------------------------------------------------------------------
// Kernel 3: per-row BN+ReLU, head logits, argmax (proven in round 1)
// ---------------------------------------------------------------------------
__global__ __launch_bounds__(256)
void heads_kernel(const float* __restrict__ Wa, const float* __restrict__ ba,
                  const float* __restrict__ Wb, const float* __restrict__ bb,
                  float* __restrict__ out) {
    __shared__ float4 sW[8][128];
    __shared__ float  sbias[8];

    const int tid = threadIdx.x;
    for (int i = tid; i < 8 * 128; i += 256) {
        const int c = i >> 7;
        const int f4 = i & 127;
        const int h = f4 * 4;
        float4 w;
        if (c < 3) {
            w.x = Wa[(h + 0) * 3 + c];
            w.y = Wa[(h + 1) * 3 + c];
            w.z = Wa[(h + 2) * 3 + c];
            w.w = Wa[(h + 3) * 3 + c];
        } else {
            const int cb = c - 3;
            w.x = Wb[(h + 0) * 5 + cb];
            w.y = Wb[(h + 1) * 5 + cb];
            w.z = Wb[(h + 2) * 5 + cb];
            w.w = Wb[(h + 3) * 5 + cb];
        }
        sW[c][f4] = w;
    }
    if (tid < 3)      sbias[tid] = ba[tid];
    else if (tid < 8) sbias[tid] = bb[tid - 3];
    __syncthreads();

    const int warp = tid >> 5, lane = tid & 31;

    float4 areg[4], creg[4];
    #pragma unroll
    for (int w = 0; w < 4; ++w) {
        const int col = (w * 32 + lane) * 4;
        areg[w] = *(const float4*)&g_a[col];
        creg[w] = *(const float4*)&g_c[col];
    }

    const int base = blockIdx.x * 32 + warp * 4;
    #pragma unroll 1
    for (int r = 0; r < 4; ++r) {
        const int row = base + r;
        const int node = row & (NNODES - 1);
        const int head = (node >= NNODES / 2) ? 1 : 0;
        const float4* hp = (const float4*)(g_h + (size_t)row * NDIM);

        float a0 = 0.f, a1 = 0.f, a2 = 0.f, a3 = 0.f, a4 = 0.f;
        #pragma unroll
        for (int w = 0; w < 4; ++w) {
            const int f4 = w * 32 + lane;
            const float4 hv = hp[f4];
            const float r0 = fmaxf(fmaf(hv.x, areg[w].x, creg[w].x), 0.f);
            const float r1 = fmaxf(fmaf(hv.y, areg[w].y, creg[w].y), 0.f);
            const float r2 = fmaxf(fmaf(hv.z, areg[w].z, creg[w].z), 0.f);
            const float r3 = fmaxf(fmaf(hv.w, areg[w].w, creg[w].w), 0.f);
            if (head == 0) {
                float4 w0 = sW[0][f4], w1 = sW[1][f4], w2 = sW[2][f4];
                a0 = fmaf(r0, w0.x, fmaf(r1, w0.y, fmaf(r2, w0.z, fmaf(r3, w0.w, a0))));
                a1 = fmaf(r0, w1.x, fmaf(r1, w1.y, fmaf(r2, w1.z, fmaf(r3, w1.w, a1))));
                a2 = fmaf(r0, w2.x, fmaf(r1, w2.y, fmaf(r2, w2.z, fmaf(r3, w2.w, a2))));
            } else {
                float4 w0 = sW[3][f4], w1 = sW[4][f4], w2 = sW[5][f4],
                       w3 = sW[6][f4], w4 = sW[7][f4];
                a0 = fmaf(r0, w0.x, fmaf(r1, w0.y, fmaf(r2, w0.z, fmaf(r3, w0.w, a0))));
                a1 = fmaf(r0, w1.x, fmaf(r1, w1.y, fmaf(r2, w1.z, fmaf(r3, w1.w, a1))));
                a2 = fmaf(r0, w2.x, fmaf(r1, w2.y, fmaf(r2, w2.z, fmaf(r3, w2.w, a2))));
                a3 = fmaf(r0, w3.x, fmaf(r1, w3.y, fmaf(r2, w3.z, fmaf(r3, w3.w, a3))));
                a4 = fmaf(r0, w4.x, fmaf(r1, w4.y, fmaf(r2, w4.z, fmaf(r3, w4.w, a4))));
            }
        }
        #pragma unroll
        for (int off = 16; off; off >>= 1) {
            a0 += __shfl_xor_sync(0xffffffffu, a0, off);
            a1 += __shfl_xor_sync(0xffffffffu, a1, off);
            a2 += __shfl_xor_sync(0xffffffffu, a2, off);
            a3 += __shfl_xor_sync(0xffffffffu, a3, off);
            a4 += __shfl_xor_sync(0xffffffffu, a4, off);
        }
        if (lane == 0) {
            const int cbase = head ? 3 : 0;
            const int nc = head ? 5 : 3;
            float lg[5] = {a0, a1, a2, a3, a4};
            float best = lg[0] + sbias[cbase];
            int bi = 0;
            #pragma unroll
            for (int c = 1; c < 5; ++c) {
                if (c < nc) {
                    const float v = lg[c] + sbias[cbase + c];
                    if (v > best) { best = v; bi = c; }
                }
            }
            out[row] = (float)bi;
        }
    }
}

// ---------------------------------------------------------------------------
// Launch sequence (graph-capturable: kernel launches only)
// ---------------------------------------------------------------------------
extern "C" void kernel_launch(void* const* d_in, const int* in_sizes, int n_in,
                              void* d_out, int out_size) {
    const float* x     = (const float*)d_in[0];
    const float* W1    = (const float*)d_in[1];
    const float* b1    = (const float*)d_in[2];
    const float* gamma = (const float*)d_in[3];
    const float* beta  = (const float*)d_in[4];
    const float* Wa    = (const float*)d_in[5];
    const float* ba    = (const float*)d_in[6];
    const float* Wb    = (const float*)d_in[7];
    const float* bb    = (const float*)d_in[8];
    float* out = (float*)d_out;

    cudaFuncSetAttribute(gemm_tc_kernel,
                         cudaFuncAttributeMaxDynamicSharedMemorySize, SMEM_DYN);

    split_x_kernel<<<(MROWS * KDIM) / 1024, 256>>>(x);
    split_w_kernel<<<(NDIM * KDIM) / 256, 256>>>(W1);
    init_kernel<<<2, 256>>>();
    gemm_tc_kernel<<<dim3(NDIM / BN, MROWS / BM), GTHREADS, SMEM_DYN>>>(b1);
    finalize_kernel<<<1, 512>>>(gamma, beta);
    heads_kernel<<<MROWS / 32, 256>>>(Wa, ba, Wb, bb, out);
}

// round 6
// speedup vs baseline: 2.0763x; 1.3922x over previous
#include <cuda_runtime.h>
#include <cuda_fp16.h>
#include <math.h>
#include <stdint.h>

// Problem constants (fixed by setup_inputs)
#define MROWS (64 * 2048)   // B*N = 131072
#define KDIM 512            // D
#define NDIM 512            // H
#define NNODES 2048
#define BN_EPS 1e-5

// GEMM tiling
#define BM 128
#define BN 256
#define BK 32
#define NCHUNK (KDIM / BK)     // 16
#define GTHREADS 512           // 16 warps: 2 (M) x 8 (N), warp tile 64x32
#define NSTAGE 4

// Stage layout (bytes): A0(8K) A1(8K) B0(16K) B1(16K) = 48K
#define A_PLANE     8192
#define B_OFF       16384
#define B_PLANE     16384
#define STAGE_BYTES 49152
#define SMEM_DYN    (NSTAGE * STAGE_BYTES)   // 192 KB
#define SCW 260                 // epilogue fp32 stride (128x260 = 133KB)

// Scratch (device globals: allocation-free)
__device__ float  g_h[(size_t)MROWS * NDIM];           // 256 MB
__device__ __half g_xa[2][(size_t)MROWS * KDIM];       // x splits, [m][k]
__device__ __half g_wb[2][(size_t)NDIM * KDIM];        // W1^T splits, [n][k]
__device__ double g_sum[NDIM];
__device__ double g_sumsq[NDIM];
__device__ float  g_a[NDIM];
__device__ float  g_c[NDIM];

// ---------------------------------------------------------------------------
// PTX helpers (base-target instructions only)
// ---------------------------------------------------------------------------
__device__ __forceinline__ uint32_t smem_u32(const void* p) {
    return (uint32_t)__cvta_generic_to_shared(p);
}

#define CP_ASYNC16(dst, src) \
    asm volatile("cp.async.cg.shared.global [%0], [%1], 16;" :: "r"(dst), "l"(src))
#define CP_COMMIT() asm volatile("cp.async.commit_group;" ::: "memory")
#define CP_WAIT(n)  asm volatile("cp.async.wait_group %0;" :: "n"(n) : "memory")

__device__ __forceinline__ void ldsm4(uint32_t& r0, uint32_t& r1,
                                      uint32_t& r2, uint32_t& r3, uint32_t addr) {
    asm volatile("ldmatrix.sync.aligned.m8n8.x4.shared.b16 {%0,%1,%2,%3}, [%4];"
                 : "=r"(r0), "=r"(r1), "=r"(r2), "=r"(r3) : "r"(addr));
}

__device__ __forceinline__ void mma16816(float* c, const uint32_t* a, const uint32_t* b) {
    asm volatile(
        "mma.sync.aligned.m16n8k16.row.col.f32.f16.f16.f32 "
        "{%0,%1,%2,%3}, {%4,%5,%6,%7}, {%8,%9}, {%0,%1,%2,%3};"
        : "+f"(c[0]), "+f"(c[1]), "+f"(c[2]), "+f"(c[3])
        : "r"(a[0]), "r"(a[1]), "r"(a[2]), "r"(a[3]), "r"(b[0]), "r"(b[1]));
}

// Folded tile layout: logical row r (64B) lives at smem row R=r>>1, half (r&1).
// f(r,seg) = R*128 + ((((r&1)<<6) | seg) ^ ((R&7)<<4)); conflict-free for LDSM.
__device__ __forceinline__ uint32_t fold_off(int r, int seg) {
    int R = r >> 1;
    return (uint32_t)(R * 128 + ((((r & 1) << 6) | seg) ^ ((R & 7) << 4)));
}

// ---------------------------------------------------------------------------
// fp32 -> 2x fp16 split kernels
// ---------------------------------------------------------------------------
union HF4 { __half h[4]; uint2 u; };

__global__ __launch_bounds__(256) void split_x_kernel(const float* __restrict__ x) {
    size_t i = ((size_t)blockIdx.x * 256 + threadIdx.x) * 4;
    float4 v = *(const float4*)(x + i);
    float f[4] = {v.x, v.y, v.z, v.w};
    HF4 p0, p1;
    #pragma unroll
    for (int j = 0; j < 4; ++j) {
        __half h0 = __float2half_rn(f[j]);
        float r = f[j] - __half2float(h0);
        p0.h[j] = h0;
        p1.h[j] = __float2half_rn(r);
    }
    *(uint2*)&g_xa[0][i] = p0.u;
    *(uint2*)&g_xa[1][i] = p1.u;
}

// W1 [K, N] -> transposed split planes [n][k]
__global__ __launch_bounds__(256) void split_w_kernel(const float* __restrict__ W1) {
    int idx = blockIdx.x * 256 + threadIdx.x;   // idx = n*512 + k
    int n = idx >> 9, k = idx & 511;
    float t = W1[(size_t)k * NDIM + n];
    __half h0 = __float2half_rn(t);
    float r = t - __half2float(h0);
    g_wb[0][idx] = h0;
    g_wb[1][idx] = __float2half_rn(r);
}

// ---------------------------------------------------------------------------
// Kernel 0: zero stats accumulators (reset on every graph replay)
// ---------------------------------------------------------------------------
__global__ void init_kernel() {
    int t = blockIdx.x * blockDim.x + threadIdx.x;
    if (t < NDIM) { g_sum[t] = 0.0; g_sumsq[t] = 0.0; }
}

// ---------------------------------------------------------------------------
// GEMM: h = x @ W1 + b1, 3-product fp16x2 emulation on mma.sync.
// 128x256 CTA tile, BK=32, 4-stage cp.async pipeline (issue-before-compute).
// Fused epilogue: bias, store h, column sum/sumsq (fp64 atomics).
// ---------------------------------------------------------------------------
__global__ __launch_bounds__(GTHREADS, 1)
void gemm_tc_kernel(const float* __restrict__ bias) {
    extern __shared__ char dynsmem[];
    __shared__ float sbias[BN];

    const int tid = threadIdx.x;
    const int bn = blockIdx.x * BN;
    const int bm = blockIdx.y * BM;
    const uint32_t sbase = smem_u32(dynsmem);

    if (tid < BN) sbias[tid] = bias[bn + tid];

    // ---- hoisted cp.async addressing (only kt varies in the loop) ----
    const int cr  = tid >> 2;            // row 0..127
    const int seg = (tid & 3) * 16;      // 16B segment in 64B logical row
    const uint32_t fA = fold_off(cr, seg);          // also B chunk0; B chunk1 = fA + 8192
    const char* aSrc0 = (const char*)g_xa[0] + ((size_t)(bm + cr) * KDIM) * 2 + seg;
    const char* aSrc1 = (const char*)g_xa[1] + ((size_t)(bm + cr) * KDIM) * 2 + seg;
    const char* bSrc0 = (const char*)g_wb[0] + ((size_t)(bn + cr) * KDIM) * 2 + seg;
    const char* bSrc1 = (const char*)g_wb[1] + ((size_t)(bn + cr) * KDIM) * 2 + seg;
    const char* bSrc0b = bSrc0 + (size_t)128 * KDIM * 2;
    const char* bSrc1b = bSrc1 + (size_t)128 * KDIM * 2;

    #define ISSUE_LOADS(stg, kt) do {                                   \
        const uint32_t so = sbase + (stg) * STAGE_BYTES;                \
        const size_t kb = (size_t)(kt) * (BK * 2);                      \
        CP_ASYNC16(so + fA,                    aSrc0 + kb);             \
        CP_ASYNC16(so + A_PLANE + fA,          aSrc1 + kb);             \
        CP_ASYNC16(so + B_OFF + fA,            bSrc0 + kb);             \
        CP_ASYNC16(so + B_OFF + 8192 + fA,     bSrc0b + kb);            \
        CP_ASYNC16(so + B_OFF + B_PLANE + fA,  bSrc1 + kb);             \
        CP_ASYNC16(so + B_OFF + B_PLANE + 8192 + fA, bSrc1b + kb);      \
        CP_COMMIT();                                                    \
    } while (0)

    // ---- warp/lane fragment addressing (lane-constant swizzle) ----
    const int wid = tid >> 5, l = tid & 31;
    const int wm = wid >> 3;           // 0..1
    const int wn = wid & 7;            // 0..7
    const int la = l & 15;             // A logical row within 16
    const int ca = (l >> 4) * 16;      // A k-chunk byte
    const int ln = (l & 7) + ((l >> 4) << 3);   // B logical row within 16
    const int kb = ((l >> 3) & 1) * 16;         // B k-chunk byte
    // row-dependent parts: R&7 == (la>>1)&7 (mi*8 multiples vanish)
    const uint32_t aRow = (uint32_t)((wm * 32 + (la >> 1)) * 128);
    const uint32_t bRow = (uint32_t)((wn * 16 + (ln >> 1)) * 128);
    const uint32_t sxA = (uint32_t)(((la >> 1) & 7) << 4);
    const uint32_t sxB = (uint32_t)(((ln >> 1) & 7) << 4);
    const uint32_t aHalf = (uint32_t)((la & 1) << 6);
    const uint32_t bHalf = (uint32_t)((ln & 1) << 6);

    float c[4][4][4];
    #pragma unroll
    for (int mi = 0; mi < 4; ++mi)
        #pragma unroll
        for (int nj = 0; nj < 4; ++nj)
            #pragma unroll
            for (int r = 0; r < 4; ++r) c[mi][nj][r] = 0.f;

    // prologue: fill 3 stages
    ISSUE_LOADS(0, 0);
    ISSUE_LOADS(1, 1);
    ISSUE_LOADS(2, 2);

    #pragma unroll 1
    for (int kt = 0; kt < NCHUNK; ++kt) {
        const int st = kt & 3;
        if (kt <= NCHUNK - 3)      { CP_WAIT(2); }
        else if (kt == NCHUNK - 2) { CP_WAIT(1); }
        else                       { CP_WAIT(0); }
        __syncthreads();
        if (kt + 3 < NCHUNK) ISSUE_LOADS((kt + 3) & 3, kt + 3);

        const uint32_t so = sbase + st * STAGE_BYTES;
        #pragma unroll
        for (int ks = 0; ks < 2; ++ks) {
            const uint32_t aCol = (aHalf + ks * 32 + ca) ^ sxA;
            const uint32_t bCol = (bHalf + ks * 32 + kb) ^ sxB;
            const uint32_t aB = so + aRow + aCol;
            const uint32_t bB = so + B_OFF + bRow + bCol;

            uint32_t b0[2][4], b1[2][4], a[4][4];
            #pragma unroll
            for (int jj = 0; jj < 2; ++jj) {
                ldsm4(b0[jj][0], b0[jj][1], b0[jj][2], b0[jj][3], bB + jj * 1024);
                ldsm4(b1[jj][0], b1[jj][1], b1[jj][2], b1[jj][3], bB + B_PLANE + jj * 1024);
            }
            #pragma unroll
            for (int mi = 0; mi < 4; ++mi)
                ldsm4(a[mi][0], a[mi][1], a[mi][2], a[mi][3], aB + mi * 1024);
            // p0: x0*w0, p1: x0*w1
            #pragma unroll
            for (int mi = 0; mi < 4; ++mi) {
                mma16816(c[mi][0], a[mi], &b0[0][0]);
                mma16816(c[mi][1], a[mi], &b0[0][2]);
                mma16816(c[mi][2], a[mi], &b0[1][0]);
                mma16816(c[mi][3], a[mi], &b0[1][2]);
            }
            #pragma unroll
            for (int mi = 0; mi < 4; ++mi) {
                mma16816(c[mi][0], a[mi], &b1[0][0]);
                mma16816(c[mi][1], a[mi], &b1[0][2]);
                mma16816(c[mi][2], a[mi], &b1[1][0]);
                mma16816(c[mi][3], a[mi], &b1[1][2]);
            }
            // p2: x1*w0 (reload A plane 1 into same regs)
            #pragma unroll
            for (int mi = 0; mi < 4; ++mi)
                ldsm4(a[mi][0], a[mi][1], a[mi][2], a[mi][3], aB + A_PLANE + mi * 1024);
            #pragma unroll
            for (int mi = 0; mi < 4; ++mi) {
                mma16816(c[mi][0], a[mi], &b0[0][0]);
                mma16816(c[mi][1], a[mi], &b0[0][2]);
                mma16816(c[mi][2], a[mi], &b0[1][0]);
                mma16816(c[mi][3], a[mi], &b0[1][2]);
            }
        }
    }
    __syncthreads();

    // ---------------- epilogue: accum -> smem (bias added) ----------------
    float* sC = (float*)dynsmem;
    const int qrow = l >> 2, qcol = (l & 3) * 2;
    #pragma unroll
    for (int mi = 0; mi < 4; ++mi) {
        #pragma unroll
        for (int nj = 0; nj < 4; ++nj) {
            const int m = wm * 64 + mi * 16 + qrow;
            const int n = wn * 32 + nj * 8 + qcol;
            const float b0 = sbias[n], b1 = sbias[n + 1];
            float2 v01 = make_float2(c[mi][nj][0] + b0, c[mi][nj][1] + b1);
            float2 v23 = make_float2(c[mi][nj][2] + b0, c[mi][nj][3] + b1);
            *(float2*)&sC[m * SCW + n] = v01;
            *(float2*)&sC[(m + 8) * SCW + n] = v23;
        }
    }
    __syncthreads();

    // store h (coalesced): thread -> (row, 64-col segment)
    {
        const int row = tid >> 2;
        const int sg = (tid & 3) * 64;
        const float* src = &sC[row * SCW + sg];
        float* dst = g_h + (size_t)(bm + row) * NDIM + bn + sg;
        #pragma unroll
        for (int q = 0; q < 16; ++q)
            *(float4*)(dst + q * 4) = *(const float4*)(src + q * 4);
    }

    // column stats: 256 threads, one column each
    if (tid < BN) {
        float s = 0.f, q = 0.f;
        #pragma unroll 8
        for (int r = 0; r < BM; ++r) {
            float t = sC[r * SCW + tid];
            s += t;
            q = fmaf(t, t, q);
        }
        atomicAdd(&g_sum[bn + tid], (double)s);
        atomicAdd(&g_sumsq[bn + tid], (double)q);
    }
    #undef ISSUE_LOADS
}

// ---------------------------------------------------------------------------
// Kernel 2: finalize BN affine params
// ---------------------------------------------------------------------------
__global__ void finalize_kernel(const float* __restrict__ gamma,
                                const float* __restrict__ beta) {
    const int t = threadIdx.x;  // 512 threads, 1 block
    const double mu  = g_sum[t]   / (double)MROWS;
    const double var = g_sumsq[t] / (double)MROWS - mu * mu;
    const float a = gamma[t] * (float)(1.0 / sqrt(var + BN_EPS));
    g_a[t] = a;
    g_c[t] = beta[t] - (float)mu * a;
}

// ---------------------------------------------------------------------------
// Kernel 3: per-row BN+ReLU, head logits, argmax (proven in rounds 1/5)
// ---------------------------------------------------------------------------
__global__ __launch_bounds__(256)
void heads_kernel(const float* __restrict__ Wa, const float* __restrict__ ba,
                  const float* __restrict__ Wb, const float* __restrict__ bb,
                  float* __restrict__ out) {
    __shared__ float4 sW[8][128];
    __shared__ float  sbias[8];

    const int tid = threadIdx.x;
    for (int i = tid; i < 8 * 128; i += 256) {
        const int c = i >> 7;
        const int f4 = i & 127;
        const int h = f4 * 4;
        float4 w;
        if (c < 3) {
            w.x = Wa[(h + 0) * 3 + c];
            w.y = Wa[(h + 1) * 3 + c];
            w.z = Wa[(h + 2) * 3 + c];
            w.w = Wa[(h + 3) * 3 + c];
        } else {
            const int cb = c - 3;
            w.x = Wb[(h + 0) * 5 + cb];
            w.y = Wb[(h + 1) * 5 + cb];
            w.z = Wb[(h + 2) * 5 + cb];
            w.w = Wb[(h + 3) * 5 + cb];
        }
        sW[c][f4] = w;
    }
    if (tid < 3)      sbias[tid] = ba[tid];
    else if (tid < 8) sbias[tid] = bb[tid - 3];
    __syncthreads();

    const int warp = tid >> 5, lane = tid & 31;

    float4 areg[4], creg[4];
    #pragma unroll
    for (int w = 0; w < 4; ++w) {
        const int col = (w * 32 + lane) * 4;
        areg[w] = *(const float4*)&g_a[col];
        creg[w] = *(const float4*)&g_c[col];
    }

    const int base = blockIdx.x * 32 + warp * 4;
    #pragma unroll 1
    for (int r = 0; r < 4; ++r) {
        const int row = base + r;
        const int node = row & (NNODES - 1);
        const int head = (node >= NNODES / 2) ? 1 : 0;
        const float4* hp = (const float4*)(g_h + (size_t)row * NDIM);

        float a0 = 0.f, a1 = 0.f, a2 = 0.f, a3 = 0.f, a4 = 0.f;
        #pragma unroll
        for (int w = 0; w < 4; ++w) {
            const int f4 = w * 32 + lane;
            const float4 hv = hp[f4];
            const float r0 = fmaxf(fmaf(hv.x, areg[w].x, creg[w].x), 0.f);
            const float r1 = fmaxf(fmaf(hv.y, areg[w].y, creg[w].y), 0.f);
            const float r2 = fmaxf(fmaf(hv.z, areg[w].z, creg[w].z), 0.f);
            const float r3 = fmaxf(fmaf(hv.w, areg[w].w, creg[w].w), 0.f);
            if (head == 0) {
                float4 w0 = sW[0][f4], w1 = sW[1][f4], w2 = sW[2][f4];
                a0 = fmaf(r0, w0.x, fmaf(r1, w0.y, fmaf(r2, w0.z, fmaf(r3, w0.w, a0))));
                a1 = fmaf(r0, w1.x, fmaf(r1, w1.y, fmaf(r2, w1.z, fmaf(r3, w1.w, a1))));
                a2 = fmaf(r0, w2.x, fmaf(r1, w2.y, fmaf(r2, w2.z, fmaf(r3, w2.w, a2))));
            } else {
                float4 w0 = sW[3][f4], w1 = sW[4][f4], w2 = sW[5][f4],
                       w3 = sW[6][f4], w4 = sW[7][f4];
                a0 = fmaf(r0, w0.x, fmaf(r1, w0.y, fmaf(r2, w0.z, fmaf(r3, w0.w, a0))));
                a1 = fmaf(r0, w1.x, fmaf(r1, w1.y, fmaf(r2, w1.z, fmaf(r3, w1.w, a1))));
                a2 = fmaf(r0, w2.x, fmaf(r1, w2.y, fmaf(r2, w2.z, fmaf(r3, w2.w, a2))));
                a3 = fmaf(r0, w3.x, fmaf(r1, w3.y, fmaf(r2, w3.z, fmaf(r3, w3.w, a3))));
                a4 = fmaf(r0, w4.x, fmaf(r1, w4.y, fmaf(r2, w4.z, fmaf(r3, w4.w, a4))));
            }
        }
        #pragma unroll
        for (int off = 16; off; off >>= 1) {
            a0 += __shfl_xor_sync(0xffffffffu, a0, off);
            a1 += __shfl_xor_sync(0xffffffffu, a1, off);
            a2 += __shfl_xor_sync(0xffffffffu, a2, off);
            a3 += __shfl_xor_sync(0xffffffffu, a3, off);
            a4 += __shfl_xor_sync(0xffffffffu, a4, off);
        }
        if (lane == 0) {
            const int cbase = head ? 3 : 0;
            const int nc = head ? 5 : 3;
            float lg[5] = {a0, a1, a2, a3, a4};
            float best = lg[0] + sbias[cbase];
            int bi = 0;
            #pragma unroll
            for (int c = 1; c < 5; ++c) {
                if (c < nc) {
                    const float v = lg[c] + sbias[cbase + c];
                    if (v > best) { best = v; bi = c; }
                }
            }
            out[row] = (float)bi;
        }
    }
}

// ---------------------------------------------------------------------------
// Launch sequence (graph-capturable: kernel launches only)
// ---------------------------------------------------------------------------
extern "C" void kernel_launch(void* const* d_in, const int* in_sizes, int n_in,
                              void* d_out, int out_size) {
    const float* x     = (const float*)d_in[0];
    const float* W1    = (const float*)d_in[1];
    const float* b1    = (const float*)d_in[2];
    const float* gamma = (const float*)d_in[3];
    const float* beta  = (const float*)d_in[4];
    const float* Wa    = (const float*)d_in[5];
    const float* ba    = (const float*)d_in[6];
    const float* Wb    = (const float*)d_in[7];
    const float* bb    = (const float*)d_in[8];
    float* out = (float*)d_out;

    cudaFuncSetAttribute(gemm_tc_kernel,
                         cudaFuncAttributeMaxDynamicSharedMemorySize, SMEM_DYN);

    split_x_kernel<<<(MROWS * KDIM) / 1024, 256>>>(x);
    split_w_kernel<<<(NDIM * KDIM) / 256, 256>>>(W1);
    init_kernel<<<2, 256>>>();
    gemm_tc_kernel<<<dim3(NDIM / BN, MROWS / BM), GTHREADS, SMEM_DYN>>>(b1);
    finalize_kernel<<<1, 512>>>(gamma, beta);
    heads_kernel<<<MROWS / 32, 256>>>(Wa, ba, Wb, bb, out);
}

// round 9
// speedup vs baseline: 2.2735x; 1.0950x over previous
#include <cuda_runtime.h>
#include <cuda_fp16.h>
#include <math.h>
#include <stdint.h>

// Problem constants (fixed by setup_inputs)
#define MROWS (64 * 2048)   // B*N = 131072
#define KDIM 512            // D
#define NDIM 512            // H
#define NNODES 2048
#define BN_EPS 1e-5

// GEMM tiling: 128x128 CTA tile, 2 CTAs/SM
#define BM 128
#define BN 128
#define BK 32
#define NCHUNK (KDIM / BK)     // 16
#define GTHREADS 256           // 8 warps: 2 (M) x 4 (N), warp tile 64x32
#define NSTAGE 3

// Stage layout (bytes): A0(8K) A1(8K) B0(8K) B1(8K) = 32K
#define A_PLANE     8192
#define B_OFF       16384
#define B_PLANE     8192
#define STAGE_BYTES 32768
#define SMEM_DYN    (NSTAGE * STAGE_BYTES)   // 96 KB -> 2 CTAs/SM
#define SCW 132                 // epilogue fp32 stride (128x132x4 = 67.6KB)

// Scratch (device globals: allocation-free)
__device__ float  g_h[(size_t)MROWS * NDIM];           // 256 MB
__device__ __half g_xa[2][(size_t)MROWS * KDIM];       // x splits, [m][k]
__device__ __half g_wb[2][(size_t)NDIM * KDIM];        // W1^T splits, [n][k]
__device__ double g_sum[NDIM];
__device__ double g_sumsq[NDIM];
__device__ float  g_a[NDIM];
__device__ float  g_c[NDIM];

// ---------------------------------------------------------------------------
// PTX helpers (base-target instructions only)
// ---------------------------------------------------------------------------
__device__ __forceinline__ uint32_t smem_u32(const void* p) {
    return (uint32_t)__cvta_generic_to_shared(p);
}

#define CP_ASYNC16(dst, src) \
    asm volatile("cp.async.cg.shared.global [%0], [%1], 16;" :: "r"(dst), "l"(src))
#define CP_COMMIT() asm volatile("cp.async.commit_group;" ::: "memory")
#define CP_WAIT(n)  asm volatile("cp.async.wait_group %0;" :: "n"(n) : "memory")

__device__ __forceinline__ void ldsm4(uint32_t& r0, uint32_t& r1,
                                      uint32_t& r2, uint32_t& r3, uint32_t addr) {
    asm volatile("ldmatrix.sync.aligned.m8n8.x4.shared.b16 {%0,%1,%2,%3}, [%4];"
                 : "=r"(r0), "=r"(r1), "=r"(r2), "=r"(r3) : "r"(addr));
}

__device__ __forceinline__ void mma16816(float* c, const uint32_t* a, const uint32_t* b) {
    asm volatile(
        "mma.sync.aligned.m16n8k16.row.col.f32.f16.f16.f32 "
        "{%0,%1,%2,%3}, {%4,%5,%6,%7}, {%8,%9}, {%0,%1,%2,%3};"
        : "+f"(c[0]), "+f"(c[1]), "+f"(c[2]), "+f"(c[3])
        : "r"(a[0]), "r"(a[1]), "r"(a[2]), "r"(a[3]), "r"(b[0]), "r"(b[1]));
}

// Folded tile layout: logical row r (64B) lives at smem row R=r>>1, half (r&1).
// f(r,seg) = R*128 + ((((r&1)<<6) | seg) ^ ((R&7)<<4)); conflict-free for LDSM.
__device__ __forceinline__ uint32_t fold_off(int r, int seg) {
    int R = r >> 1;
    return (uint32_t)(R * 128 + ((((r & 1) << 6) | seg) ^ ((R & 7) << 4)));
}

// ---------------------------------------------------------------------------
// fp32 -> 2x fp16 split kernels
// ---------------------------------------------------------------------------
union HF4 { __half h[4]; uint2 u; };

__global__ __launch_bounds__(256) void split_x_kernel(const float* __restrict__ x) {
    size_t i = ((size_t)blockIdx.x * 256 + threadIdx.x) * 4;
    float4 v = *(const float4*)(x + i);
    float f[4] = {v.x, v.y, v.z, v.w};
    HF4 p0, p1;
    #pragma unroll
    for (int j = 0; j < 4; ++j) {
        __half h0 = __float2half_rn(f[j]);
        float r = f[j] - __half2float(h0);
        p0.h[j] = h0;
        p1.h[j] = __float2half_rn(r);
    }
    *(uint2*)&g_xa[0][i] = p0.u;
    *(uint2*)&g_xa[1][i] = p1.u;
}

// W1 [K, N] -> transposed split planes [n][k]
__global__ __launch_bounds__(256) void split_w_kernel(const float* __restrict__ W1) {
    int idx = blockIdx.x * 256 + threadIdx.x;   // idx = n*512 + k
    int n = idx >> 9, k = idx & 511;
    float t = W1[(size_t)k * NDIM + n];
    __half h0 = __float2half_rn(t);
    float r = t - __half2float(h0);
    g_wb[0][idx] = h0;
    g_wb[1][idx] = __float2half_rn(r);
}

// ---------------------------------------------------------------------------
// Kernel 0: zero stats accumulators (reset on every graph replay)
// ---------------------------------------------------------------------------
__global__ void init_kernel() {
    int t = blockIdx.x * blockDim.x + threadIdx.x;
    if (t < NDIM) { g_sum[t] = 0.0; g_sumsq[t] = 0.0; }
}

// ---------------------------------------------------------------------------
// GEMM: h = x @ W1 + b1, 3-product fp16x2 emulation on mma.sync.
// 128x128 CTA tile, BK=32, 3-stage cp.async pipeline (lookahead 2: the barrier
// at the top of iteration kt orders compute of kt-1 before stage (kt+2)%3 is
// overwritten), 2 CTAs/SM.
// Fused epilogue: bias, store h, column sum/sumsq (fp64 atomics).
// ---------------------------------------------------------------------------
__global__ __launch_bounds__(GTHREADS, 2)
void gemm_tc_kernel(const float* __restrict__ bias) {
    extern __shared__ char dynsmem[];
    __shared__ float sbias[BN];

    const int tid = threadIdx.x;
    const int bn = blockIdx.x * BN;
    const int bm = blockIdx.y * BM;
    const uint32_t sbase = smem_u32(dynsmem);

    if (tid < BN) sbias[tid] = bias[bn + tid];

    // ---- hoisted cp.async addressing (only kt varies in the loop) ----
    // per plane: 128 rows x 4 segs = 512 chunks; thread does rows r0 and r0+64
    const int r0  = tid >> 2;            // rows 0..63
    const int seg = (tid & 3) * 16;
    const uint32_t fA0 = fold_off(r0, seg);
    const uint32_t fA1 = fold_off(r0 + 64, seg);
    const size_t rowB = (size_t)64 * KDIM * 2;   // +64 rows in bytes
    const char* aSrc0 = (const char*)g_xa[0] + ((size_t)(bm + r0) * KDIM) * 2 + seg;
    const char* aSrc1 = (const char*)g_xa[1] + ((size_t)(bm + r0) * KDIM) * 2 + seg;
    const char* bSrc0 = (const char*)g_wb[0] + ((size_t)(bn + r0) * KDIM) * 2 + seg;
    const char* bSrc1 = (const char*)g_wb[1] + ((size_t)(bn + r0) * KDIM) * 2 + seg;

    #define ISSUE_LOADS(stg, kt) do {                                   \
        const uint32_t so = sbase + (stg) * STAGE_BYTES;                \
        const size_t kb2 = (size_t)(kt) * (BK * 2);                     \
        CP_ASYNC16(so + fA0,                   aSrc0 + kb2);            \
        CP_ASYNC16(so + fA1,                   aSrc0 + rowB + kb2);     \
        CP_ASYNC16(so + A_PLANE + fA0,         aSrc1 + kb2);            \
        CP_ASYNC16(so + A_PLANE + fA1,         aSrc1 + rowB + kb2);     \
        CP_ASYNC16(so + B_OFF + fA0,           bSrc0 + kb2);            \
        CP_ASYNC16(so + B_OFF + fA1,           bSrc0 + rowB + kb2);     \
        CP_ASYNC16(so + B_OFF + B_PLANE + fA0, bSrc1 + kb2);            \
        CP_ASYNC16(so + B_OFF + B_PLANE + fA1, bSrc1 + rowB + kb2);     \
        CP_COMMIT();                                                    \
    } while (0)

    // ---- warp/lane fragment addressing (lane-constant swizzle) ----
    const int wid = tid >> 5, l = tid & 31;
    const int wm = wid >> 2;           // 0..1 -> m offset 64
    const int wn = wid & 3;            // 0..3 -> n offset 32
    const int la = l & 15;             // A logical row within 16
    const int ca = (l >> 4) * 16;      // A k-chunk byte
    const int ln = (l & 7) + ((l >> 4) << 3);   // B logical row within 16
    const int kb = ((l >> 3) & 1) * 16;         // B k-chunk byte
    const uint32_t aRow = (uint32_t)((wm * 32 + (la >> 1)) * 128);
    const uint32_t bRow = (uint32_t)((wn * 16 + (ln >> 1)) * 128);
    const uint32_t sxA = (uint32_t)(((la >> 1) & 7) << 4);
    const uint32_t sxB = (uint32_t)(((ln >> 1) & 7) << 4);
    const uint32_t aHalf = (uint32_t)((la & 1) << 6);
    const uint32_t bHalf = (uint32_t)((ln & 1) << 6);

    float c[4][4][4];
    #pragma unroll
    for (int mi = 0; mi < 4; ++mi)
        #pragma unroll
        for (int nj = 0; nj < 4; ++nj)
            #pragma unroll
            for (int r = 0; r < 4; ++r) c[mi][nj][r] = 0.f;

    // prologue: fill 2 stages only (3rd stage is the in-loop lookahead target)
    ISSUE_LOADS(0, 0);
    ISSUE_LOADS(1, 1);

    #pragma unroll 1
    for (int kt = 0; kt < NCHUNK; ++kt) {
        const int st = kt % 3;
        if (kt < NCHUNK - 1) { CP_WAIT(1); } else { CP_WAIT(0); }
        __syncthreads();
        if (kt + 2 < NCHUNK) ISSUE_LOADS((kt + 2) % 3, kt + 2);

        const uint32_t so = sbase + st * STAGE_BYTES;
        #pragma unroll
        for (int ks = 0; ks < 2; ++ks) {
            const uint32_t aCol = (aHalf + ks * 32 + ca) ^ sxA;
            const uint32_t bCol = (bHalf + ks * 32 + kb) ^ sxB;
            const uint32_t aB = so + aRow + aCol;
            const uint32_t bB = so + B_OFF + bRow + bCol;

            uint32_t b0[2][4], b1[2][4], a[4][4];
            #pragma unroll
            for (int jj = 0; jj < 2; ++jj) {
                ldsm4(b0[jj][0], b0[jj][1], b0[jj][2], b0[jj][3], bB + jj * 1024);
                ldsm4(b1[jj][0], b1[jj][1], b1[jj][2], b1[jj][3], bB + B_PLANE + jj * 1024);
            }
            #pragma unroll
            for (int mi = 0; mi < 4; ++mi)
                ldsm4(a[mi][0], a[mi][1], a[mi][2], a[mi][3], aB + mi * 1024);
            // p0: x0*w0, p1: x0*w1
            #pragma unroll
            for (int mi = 0; mi < 4; ++mi) {
                mma16816(c[mi][0], a[mi], &b0[0][0]);
                mma16816(c[mi][1], a[mi], &b0[0][2]);
                mma16816(c[mi][2], a[mi], &b0[1][0]);
                mma16816(c[mi][3], a[mi], &b0[1][2]);
            }
            #pragma unroll
            for (int mi = 0; mi < 4; ++mi) {
                mma16816(c[mi][0], a[mi], &b1[0][0]);
                mma16816(c[mi][1], a[mi], &b1[0][2]);
                mma16816(c[mi][2], a[mi], &b1[1][0]);
                mma16816(c[mi][3], a[mi], &b1[1][2]);
            }
            // p2: x1*w0 (reload A plane 1 into same regs)
            #pragma unroll
            for (int mi = 0; mi < 4; ++mi)
                ldsm4(a[mi][0], a[mi][1], a[mi][2], a[mi][3], aB + A_PLANE + mi * 1024);
            #pragma unroll
            for (int mi = 0; mi < 4; ++mi) {
                mma16816(c[mi][0], a[mi], &b0[0][0]);
                mma16816(c[mi][1], a[mi], &b0[0][2]);
                mma16816(c[mi][2], a[mi], &b0[1][0]);
                mma16816(c[mi][3], a[mi], &b0[1][2]);
            }
        }
    }
    __syncthreads();

    // ---------------- epilogue: accum -> smem (bias added) ----------------
    float* sC = (float*)dynsmem;
    const int qrow = l >> 2, qcol = (l & 3) * 2;
    #pragma unroll
    for (int mi = 0; mi < 4; ++mi) {
        #pragma unroll
        for (int nj = 0; nj < 4; ++nj) {
            const int m = wm * 64 + mi * 16 + qrow;
            const int n = wn * 32 + nj * 8 + qcol;
            const float b0 = sbias[n], b1 = sbias[n + 1];
            float2 v01 = make_float2(c[mi][nj][0] + b0, c[mi][nj][1] + b1);
            float2 v23 = make_float2(c[mi][nj][2] + b0, c[mi][nj][3] + b1);
            *(float2*)&sC[m * SCW + n] = v01;
            *(float2*)&sC[(m + 8) * SCW + n] = v23;
        }
    }
    __syncthreads();

    // store h (coalesced): thread -> (row, 64-col segment), 128x128 tile
    {
        const int row = tid >> 1;
        const int sg = (tid & 1) * 64;
        const float* src = &sC[row * SCW + sg];
        float* dst = g_h + (size_t)(bm + row) * NDIM + bn + sg;
        #pragma unroll
        for (int q = 0; q < 16; ++q)
            *(float4*)(dst + q * 4) = *(const float4*)(src + q * 4);
    }

    // column stats: 128 threads, one column each
    if (tid < BN) {
        float s = 0.f, q = 0.f;
        #pragma unroll 8
        for (int r = 0; r < BM; ++r) {
            float t = sC[r * SCW + tid];
            s += t;
            q = fmaf(t, t, q);
        }
        atomicAdd(&g_sum[bn + tid], (double)s);
        atomicAdd(&g_sumsq[bn + tid], (double)q);
    }
    #undef ISSUE_LOADS
}

// ---------------------------------------------------------------------------
// Kernel 2: finalize BN affine params
// ---------------------------------------------------------------------------
__global__ void finalize_kernel(const float* __restrict__ gamma,
                                const float* __restrict__ beta) {
    const int t = threadIdx.x;  // 512 threads, 1 block
    const double mu  = g_sum[t]   / (double)MROWS;
    const double var = g_sumsq[t] / (double)MROWS - mu * mu;
    const float a = gamma[t] * (float)(1.0 / sqrt(var + BN_EPS));
    g_a[t] = a;
    g_c[t] = beta[t] - (float)mu * a;
}

// ---------------------------------------------------------------------------
// Kernel 3: per-row BN+ReLU, head logits, argmax (proven in rounds 1/5/6)
// ---------------------------------------------------------------------------
__global__ __launch_bounds__(256)
void heads_kernel(const float* __restrict__ Wa, const float* __restrict__ ba,
                  const float* __restrict__ Wb, const float* __restrict__ bb,
                  float* __restrict__ out) {
    __shared__ float4 sW[8][128];
    __shared__ float  sbias[8];

    const int tid = threadIdx.x;
    for (int i = tid; i < 8 * 128; i += 256) {
        const int c = i >> 7;
        const int f4 = i & 127;
        const int h = f4 * 4;
        float4 w;
        if (c < 3) {
            w.x = Wa[(h + 0) * 3 + c];
            w.y = Wa[(h + 1) * 3 + c];
            w.z = Wa[(h + 2) * 3 + c];
            w.w = Wa[(h + 3) * 3 + c];
        } else {
            const int cb = c - 3;
            w.x = Wb[(h + 0) * 5 + cb];
            w.y = Wb[(h + 1) * 5 + cb];
            w.z = Wb[(h + 2) * 5 + cb];
            w.w = Wb[(h + 3) * 5 + cb];
        }
        sW[c][f4] = w;
    }
    if (tid < 3)      sbias[tid] = ba[tid];
    else if (tid < 8) sbias[tid] = bb[tid - 3];
    __syncthreads();

    const int warp = tid >> 5, lane = tid & 31;

    float4 areg[4], creg[4];
    #pragma unroll
    for (int w = 0; w < 4; ++w) {
        const int col = (w * 32 + lane) * 4;
        areg[w] = *(const float4*)&g_a[col];
        creg[w] = *(const float4*)&g_c[col];
    }

    const int base = blockIdx.x * 32 + warp * 4;
    #pragma unroll 1
    for (int r = 0; r < 4; ++r) {
        const int row = base + r;
        const int node = row & (NNODES - 1);
        const int head = (node >= NNODES / 2) ? 1 : 0;
        const float4* hp = (const float4*)(g_h + (size_t)row * NDIM);

        float a0 = 0.f, a1 = 0.f, a2 = 0.f, a3 = 0.f, a4 = 0.f;
        #pragma unroll
        for (int w = 0; w < 4; ++w) {
            const int f4 = w * 32 + lane;
            const float4 hv = hp[f4];
            const float r0 = fmaxf(fmaf(hv.x, areg[w].x, creg[w].x), 0.f);
            const float r1 = fmaxf(fmaf(hv.y, areg[w].y, creg[w].y), 0.f);
            const float r2 = fmaxf(fmaf(hv.z, areg[w].z, creg[w].z), 0.f);
            const float r3 = fmaxf(fmaf(hv.w, areg[w].w, creg[w].w), 0.f);
            if (head == 0) {
                float4 w0 = sW[0][f4], w1 = sW[1][f4], w2 = sW[2][f4];
                a0 = fmaf(r0, w0.x, fmaf(r1, w0.y, fmaf(r2, w0.z, fmaf(r3, w0.w, a0))));
                a1 = fmaf(r0, w1.x, fmaf(r1, w1.y, fmaf(r2, w1.z, fmaf(r3, w1.w, a1))));
                a2 = fmaf(r0, w2.x, fmaf(r1, w2.y, fmaf(r2, w2.z, fmaf(r3, w2.w, a2))));
            } else {
                float4 w0 = sW[3][f4], w1 = sW[4][f4], w2 = sW[5][f4],
                       w3 = sW[6][f4], w4 = sW[7][f4];
                a0 = fmaf(r0, w0.x, fmaf(r1, w0.y, fmaf(r2, w0.z, fmaf(r3, w0.w, a0))));
                a1 = fmaf(r0, w1.x, fmaf(r1, w1.y, fmaf(r2, w1.z, fmaf(r3, w1.w, a1))));
                a2 = fmaf(r0, w2.x, fmaf(r1, w2.y, fmaf(r2, w2.z, fmaf(r3, w2.w, a2))));
                a3 = fmaf(r0, w3.x, fmaf(r1, w3.y, fmaf(r2, w3.z, fmaf(r3, w3.w, a3))));
                a4 = fmaf(r0, w4.x, fmaf(r1, w4.y, fmaf(r2, w4.z, fmaf(r3, w4.w, a4))));
            }
        }
        #pragma unroll
        for (int off = 16; off; off >>= 1) {
            a0 += __shfl_xor_sync(0xffffffffu, a0, off);
            a1 += __shfl_xor_sync(0xffffffffu, a1, off);
            a2 += __shfl_xor_sync(0xffffffffu, a2, off);
            a3 += __shfl_xor_sync(0xffffffffu, a3, off);
            a4 += __shfl_xor_sync(0xffffffffu, a4, off);
        }
        if (lane == 0) {
            const int cbase = head ? 3 : 0;
            const int nc = head ? 5 : 3;
            float lg[5] = {a0, a1, a2, a3, a4};
            float best = lg[0] + sbias[cbase];
            int bi = 0;
            #pragma unroll
            for (int c = 1; c < 5; ++c) {
                if (c < nc) {
                    const float v = lg[c] + sbias[cbase + c];
                    if (v > best) { best = v; bi = c; }
                }
            }
            out[row] = (float)bi;
        }
    }
}

// ---------------------------------------------------------------------------
// Launch sequence (graph-capturable: kernel launches only)
// ---------------------------------------------------------------------------
extern "C" void kernel_launch(void* const* d_in, const int* in_sizes, int n_in,
                              void* d_out, int out_size) {
    const float* x     = (const float*)d_in[0];
    const float* W1    = (const float*)d_in[1];
    const float* b1    = (const float*)d_in[2];
    const float* gamma = (const float*)d_in[3];
    const float* beta  = (const float*)d_in[4];
    const float* Wa    = (const float*)d_in[5];
    const float* ba    = (const float*)d_in[6];
    const float* Wb    = (const float*)d_in[7];
    const float* bb    = (const float*)d_in[8];
    float* out = (float*)d_out;

    cudaFuncSetAttribute(gemm_tc_kernel,
                         cudaFuncAttributeMaxDynamicSharedMemorySize, SMEM_DYN);

    split_x_kernel<<<(MROWS * KDIM) / 1024, 256>>>(x);
    split_w_kernel<<<(NDIM * KDIM) / 256, 256>>>(W1);
    init_kernel<<<2, 256>>>();
    gemm_tc_kernel<<<dim3(NDIM / BN, MROWS / BM), GTHREADS, SMEM_DYN>>>(b1);
    finalize_kernel<<<1, 512>>>(gamma, beta);
    heads_kernel<<<MROWS / 32, 256>>>(Wa, ba, Wb, bb, out);
}